// round 13
// baseline (speedup 1.0000x reference)
#include <cuda_runtime.h>
#include <cuda_bf16.h>
#include <cstdint>

// Problem shape
#define T_TOK   32
#define K_IN    4096
#define N_OUT   14336

// GEMM tiling: A = weights (M=outputs), B = x (N=tokens)
#define TPB     128               // 4 warps
#define WOUT    32                // outputs per warp (2 m-tiles of 16)
#define COUT    (4 * WOUT)        // 128 outputs per CTA
#define KSPLIT  4
#define KSTEPS  (K_IN / 16)       // 256
#define KS_PER  (KSTEPS / KSPLIT) // 64 k-steps per split

// x fragments, B-operand-ready: [kstep(256)][ntile(4)][half hi/lo(2)][lane(32)] -> uint2
__device__ uint2 g_bfrag[256 * 4 * 2 * 32];            // 512 KB
__device__ float g_part[KSPLIT * T_TOK * N_OUT];       // 7.34 MB partials

// ---------------------------------------------------------------------------
// helpers
// ---------------------------------------------------------------------------
__device__ __forceinline__ float i2f_fast(int v) {   // exact for |v| < 2^22
    return __int_as_float(v + 0x4B400000) - 12582912.0f;
}

// pack two ints (int8-valued) -> bf16x2 {lo=v0, hi=v1}
__device__ __forceinline__ uint32_t cvt2bf(int v0, int v1) {
    float f0 = i2f_fast(v0);
    float f1 = i2f_fast(v1);
    uint32_t r;
    asm("cvt.rn.bf16x2.f32 %0, %1, %2;" : "=r"(r) : "f"(f1), "f"(f0)); // first src -> high
    return r;
}

__device__ __forceinline__ uint32_t packbf(__nv_bfloat16 lo, __nv_bfloat16 hi) {
    return ((uint32_t)__bfloat16_as_ushort(hi) << 16) | __bfloat16_as_ushort(lo);
}

__device__ __forceinline__ void mma_bf16(float* d,
                                         uint32_t a0, uint32_t a1, uint32_t a2, uint32_t a3,
                                         uint32_t b0, uint32_t b1) {
    asm volatile(
        "mma.sync.aligned.m16n8k16.row.col.f32.bf16.bf16.f32 "
        "{%0,%1,%2,%3}, {%4,%5,%6,%7}, {%8,%9}, {%0,%1,%2,%3};"
        : "+f"(d[0]), "+f"(d[1]), "+f"(d[2]), "+f"(d[3])
        : "r"(a0), "r"(a1), "r"(a2), "r"(a3), "r"(b0), "r"(b1));
}

// ---------------------------------------------------------------------------
// Kernel 1: build B-operand-ready x fragments (hi/lo bf16 split of x*scales)
// one thread per (kstep, ntile, lane); writes hi and lo uint2 frags
// ---------------------------------------------------------------------------
__global__ void prep_kernel(const float* __restrict__ x,
                            const float* __restrict__ scales) {
    int gtid = blockIdx.x * blockDim.x + threadIdx.x;   // 0 .. 32767
    int s    = gtid >> 7;          // kstep 0..255
    int nt   = (gtid >> 5) & 3;    // ntile 0..3
    int lane = gtid & 31;

    int t  = nt * 8 + (lane >> 2);           // token (B column)
    int k0 = s * 16 + (lane & 3) * 2;        // k rows (lane&3)*2 + {0,1} and +8

    float2 xa = *reinterpret_cast<const float2*>(&x[t * K_IN + k0]);
    float2 xb = *reinterpret_cast<const float2*>(&x[t * K_IN + k0 + 8]);
    float2 sa = *reinterpret_cast<const float2*>(&scales[k0]);
    float2 sb = *reinterpret_cast<const float2*>(&scales[k0 + 8]);

    float v0 = xa.x * sa.x, v1 = xa.y * sa.y;
    float v2 = xb.x * sb.x, v3 = xb.y * sb.y;

    __nv_bfloat16 h0 = __float2bfloat16(v0), h1 = __float2bfloat16(v1);
    __nv_bfloat16 h2 = __float2bfloat16(v2), h3 = __float2bfloat16(v3);
    __nv_bfloat16 l0 = __float2bfloat16(v0 - __bfloat162float(h0));
    __nv_bfloat16 l1 = __float2bfloat16(v1 - __bfloat162float(h1));
    __nv_bfloat16 l2 = __float2bfloat16(v2 - __bfloat162float(h2));
    __nv_bfloat16 l3 = __float2bfloat16(v3 - __bfloat162float(h3));

    int fr = (s * 4 + nt) * 2;
    g_bfrag[(fr + 0) * 32 + lane] = make_uint2(packbf(h0, h1), packbf(h2, h3));
    g_bfrag[(fr + 1) * 32 + lane] = make_uint2(packbf(l0, l1), packbf(l2, l3));
}

// ---------------------------------------------------------------------------
// Kernel 2: GEMM. warp: 32 outputs (A, from weights) x 32 tokens (B, from x)
// grid (112, KSPLIT). No smem, no syncs: pure LDG->reg->mma stream.
// ---------------------------------------------------------------------------
__global__ __launch_bounds__(TPB) void gemm_kernel(const int* __restrict__ w) {
    const int tid  = threadIdx.x;
    const int wid  = tid >> 5;
    const int lane = tid & 31;
    const int o0   = blockIdx.x * COUT + wid * WOUT;  // warp's first output row
    const int ks   = blockIdx.y;

    // this lane's weight row base (rows o0+(lane>>2) + {0,8,16,24}) and k offset
    const int kl = (lane & 3) * 2;
    const int* __restrict__ wr = w + (size_t)(o0 + (lane >> 2)) * K_IN + kl;
    const uint2* __restrict__ bf = g_bfrag + lane;

    float acc[2][4][4];
    #pragma unroll
    for (int m = 0; m < 2; m++)
        #pragma unroll
        for (int n = 0; n < 4; n++)
            #pragma unroll
            for (int r = 0; r < 4; r++) acc[m][n][r] = 0.f;

    const int s_begin = ks * KS_PER;
    #pragma unroll 2
    for (int s = s_begin; s < s_begin + KS_PER; s++) {
        const int kb = s * 16;

        // ---- weight loads: 8 x LDG.64, front-batched (A fragments, 2 m-tiles)
        int2 a00 = __ldg((const int2*)(wr + kb));                    // row r,    k
        int2 a01 = __ldg((const int2*)(wr + kb + 8));                // row r,    k+8
        int2 a10 = __ldg((const int2*)(wr + 8 * K_IN + kb));         // row r+8,  k
        int2 a11 = __ldg((const int2*)(wr + 8 * K_IN + kb + 8));
        int2 a20 = __ldg((const int2*)(wr + 16 * K_IN + kb));        // row r+16
        int2 a21 = __ldg((const int2*)(wr + 16 * K_IN + kb + 8));
        int2 a30 = __ldg((const int2*)(wr + 24 * K_IN + kb));        // row r+24
        int2 a31 = __ldg((const int2*)(wr + 24 * K_IN + kb + 8));

        // ---- x fragment loads: 8 x LDG.64 (4 ntiles x hi/lo)
        uint2 b_hi[4], b_lo[4];
        #pragma unroll
        for (int nt = 0; nt < 4; nt++) {
            b_hi[nt] = __ldg(bf + ((s * 4 + nt) * 2 + 0) * 32);
            b_lo[nt] = __ldg(bf + ((s * 4 + nt) * 2 + 1) * 32);
        }

        // ---- convert A to bf16 frags
        // frag reg layout: a0=(r,k) a1=(r+8,k) a2=(r,k+8) a3=(r+8,k+8)
        uint32_t A0[4] = { cvt2bf(a00.x, a00.y), cvt2bf(a10.x, a10.y),
                           cvt2bf(a01.x, a01.y), cvt2bf(a11.x, a11.y) };
        uint32_t A1[4] = { cvt2bf(a20.x, a20.y), cvt2bf(a30.x, a30.y),
                           cvt2bf(a21.x, a21.y), cvt2bf(a31.x, a31.y) };

        // ---- 16 mma: 2 m-tiles x 4 n-tiles x (hi + lo)
        #pragma unroll
        for (int nt = 0; nt < 4; nt++) {
            mma_bf16(acc[0][nt], A0[0], A0[1], A0[2], A0[3], b_hi[nt].x, b_hi[nt].y);
            mma_bf16(acc[0][nt], A0[0], A0[1], A0[2], A0[3], b_lo[nt].x, b_lo[nt].y);
            mma_bf16(acc[1][nt], A1[0], A1[1], A1[2], A1[3], b_hi[nt].x, b_hi[nt].y);
            mma_bf16(acc[1][nt], A1[0], A1[1], A1[2], A1[3], b_lo[nt].x, b_lo[nt].y);
        }
    }

    // ---- epilogue: partials. C frag: row(out) = lane>>2 + {0,8}, col(tok) = (lane&3)*2 + {0,1}
    #pragma unroll
    for (int mt = 0; mt < 2; mt++)
        #pragma unroll
        for (int nt = 0; nt < 4; nt++) {
            int o = o0 + mt * 16 + (lane >> 2);
            int t = nt * 8 + (lane & 3) * 2;
            float* p = &g_part[((size_t)ks * T_TOK + t) * N_OUT + o];
            p[0]                 = acc[mt][nt][0];
            p[N_OUT]             = acc[mt][nt][1];
            p[8]                 = acc[mt][nt][2];
            p[N_OUT + 8]         = acc[mt][nt][3];
        }
}

// ---------------------------------------------------------------------------
// Kernel 3: reduce K-split partials into d_out
// ---------------------------------------------------------------------------
__global__ void reduce_kernel(float* __restrict__ out) {
    int idx = blockIdx.x * blockDim.x + threadIdx.x;   // 0 .. 458751
    float s = 0.f;
    #pragma unroll
    for (int ks = 0; ks < KSPLIT; ks++)
        s += g_part[(size_t)ks * T_TOK * N_OUT + idx];
    out[idx] = s;
}

extern "C" void kernel_launch(void* const* d_in, const int* in_sizes, int n_in,
                              void* d_out, int out_size) {
    const float* x      = (const float*)d_in[0];
    const int*   weight = (const int*)d_in[1];
    const float* scales = (const float*)d_in[2];
    float* out = (float*)d_out;

    prep_kernel<<<64, 512>>>(x, scales);
    dim3 grid(N_OUT / COUT, KSPLIT);          // 112 x 4 = 448 CTAs
    gemm_kernel<<<grid, TPB>>>(weight);
    reduce_kernel<<<(T_TOK * N_OUT) / 256, 256>>>(out);
}